// round 1
// baseline (speedup 1.0000x reference)
#include <cuda_runtime.h>
#include <math.h>

#define NTOK 8192
#define DDIM 768
#define NEXP 16
#define D4   192          // DDIM/4
#define GATE_BLOCKS 256
#define EPS  1e-5f

// ---------------- device scratch (no allocations allowed) ----------------
__device__ float4 g_gate[NTOK];                    // (w0, w1, e0 bits, e1 bits)
__device__ float  g_partials[GATE_BLOCKS * 32];    // per-block soft[16] + hard[16]
__device__ float  g_scratch[NTOK * NEXP + 64];     // fallback sink if out layout != full tuple

// ---------------- kernel 1: gate logits + top-2 softmax ----------------
// 256 blocks x 256 threads; each warp handles 4 consecutive tokens so the
// W tile (48KB) is loaded once per 4 tokens (register reuse), x via float4.
__global__ __launch_bounds__(256) void gate_kernel(
    const float* __restrict__ x,
    const float* __restrict__ W,
    const float* __restrict__ b,
    float* __restrict__ s_out)
{
    __shared__ float sAcc[32];     // soft[0:16], hard[16:32]
    const int tid  = threadIdx.x;
    if (tid < 32) sAcc[tid] = 0.f;
    __syncthreads();

    const int wid  = tid >> 5;
    const int lane = tid & 31;
    const int gw   = blockIdx.x * 8 + wid;   // global warp id, 2048 warps
    const int n0   = gw * 4;                 // 4 tokens per warp

    float acc[4][NEXP];
    #pragma unroll
    for (int j = 0; j < 4; j++)
        #pragma unroll
        for (int e = 0; e < NEXP; e++) acc[j][e] = 0.f;

    const float4* x4 = (const float4*)x;
    const float4* W4 = (const float4*)W;

    #pragma unroll
    for (int i = 0; i < 6; i++) {
        const int idx = lane + 32 * i;
        float4 xv[4];
        #pragma unroll
        for (int j = 0; j < 4; j++)
            xv[j] = x4[(size_t)(n0 + j) * D4 + idx];
        #pragma unroll
        for (int e = 0; e < NEXP; e++) {
            const float4 wv = W4[e * D4 + idx];
            #pragma unroll
            for (int j = 0; j < 4; j++) {
                acc[j][e] += xv[j].x * wv.x + xv[j].y * wv.y
                           + xv[j].z * wv.z + xv[j].w * wv.w;
            }
        }
    }

    #pragma unroll
    for (int j = 0; j < 4; j++) {
        const int n = n0 + j;
        float v[NEXP];
        #pragma unroll
        for (int e = 0; e < NEXP; e++) {
            float s = acc[j][e];
            s += __shfl_xor_sync(0xffffffffu, s, 16);
            s += __shfl_xor_sync(0xffffffffu, s, 8);
            s += __shfl_xor_sync(0xffffffffu, s, 4);
            s += __shfl_xor_sync(0xffffffffu, s, 2);
            s += __shfl_xor_sync(0xffffffffu, s, 1);
            v[e] = s;
        }
        if (lane == 0) {
            #pragma unroll
            for (int e = 0; e < NEXP; e++) v[e] += b[e];

            // top-2 (ties -> lowest index first, matching lax.top_k)
            float b0 = v[0], b1 = -INFINITY;
            int   e0 = 0,    e1 = -1;
            #pragma unroll
            for (int e = 1; e < NEXP; e++) {
                if (v[e] > b0) { b1 = b0; e1 = e0; b0 = v[e]; e0 = e; }
                else if (v[e] > b1) { b1 = v[e]; e1 = e; }
            }
            // softmax over the 2 selected logits (stable: b1 <= b0)
            const float t  = expf(b1 - b0);
            const float inv = 1.f / (1.f + t);
            const float w0 = inv;
            const float w1 = t * inv;

            float4 gt;
            gt.x = w0; gt.y = w1;
            gt.z = __int_as_float(e0);
            gt.w = __int_as_float(e1);
            g_gate[n] = gt;

            // s_concat row: 1 where g < eps else 0  (g=0 for unselected)
            float4* srow = (float4*)(s_out + (size_t)n * NEXP);
            #pragma unroll
            for (int q = 0; q < 4; q++) {
                float4 sv;
                #pragma unroll
                for (int c = 0; c < 4; c++) {
                    const int e = q * 4 + c;
                    const float ge = (e == e0) ? w0 : ((e == e1) ? w1 : 0.f);
                    const float val = (ge < EPS) ? 1.f : 0.f;
                    if (c == 0) sv.x = val;
                    else if (c == 1) sv.y = val;
                    else if (c == 2) sv.z = val;
                    else sv.w = val;
                }
                srow[q] = sv;
            }

            // block-local soft/hard accumulation (shared atomics, tiny count)
            atomicAdd(&sAcc[e0], w0);
            atomicAdd(&sAcc[e1], w1);
            atomicAdd(&sAcc[16 + e0], (w0 < EPS) ? 0.f : 1.f);
            atomicAdd(&sAcc[16 + e1], (w1 < EPS) ? 0.f : 1.f);
        }
    }

    __syncthreads();
    if (tid < 32) g_partials[blockIdx.x * 32 + tid] = sAcc[tid];
}

// ---------------- kernel 2: sparse combine (the HBM-bound one) ----------------
// One block per token; 384 threads x 2 elements. Only the 2 selected expert
// values per (n,d) are touched -> only the DRAM sectors that contain them.
__global__ __launch_bounds__(384) void combine_kernel(
    const float* __restrict__ f,
    float* __restrict__ y)
{
    const int n = blockIdx.x;
    const float4 gt = g_gate[n];            // broadcast load
    const float w0 = gt.x, w1 = gt.y;
    const int   e0 = __float_as_int(gt.z);
    const int   e1 = __float_as_int(gt.w);

    const float* fr = f + (size_t)n * (DDIM * NEXP);
    float*       yr = y + (size_t)n * DDIM;

    const int d0 = threadIdx.x;
    const int d1 = threadIdx.x + 384;

    // batch all 4 loads before the stores for MLP
    const float a0 = __ldcs(fr + d0 * NEXP + e0);
    const float a1 = __ldcs(fr + d0 * NEXP + e1);
    const float c0 = __ldcs(fr + d1 * NEXP + e0);
    const float c1 = __ldcs(fr + d1 * NEXP + e1);

    yr[d0] = w0 * a0 + w1 * a1;
    yr[d1] = w0 * c0 + w1 * c1;
}

// ---------------- kernel 3: finalize averages + trailing scalar ----------------
__global__ void finalize_kernel(float* __restrict__ soft_out,
                                float* __restrict__ hard_out,
                                float* __restrict__ zero_out)
{
    const int tid = threadIdx.x;   // 32 threads
    float s = 0.f;
    for (int bb = 0; bb < GATE_BLOCKS; bb++)
        s += g_partials[bb * 32 + tid];
    s *= (1.f / (float)NTOK);
    if (tid < 16) soft_out[tid] = s;
    else          hard_out[tid - 16] = s;
    if (tid == 0) *zero_out = 0.f;
}

// ---------------- launcher ----------------
extern "C" void kernel_launch(void* const* d_in, const int* in_sizes, int n_in,
                              void* d_out, int out_size)
{
    const float* f = (const float*)d_in[0];
    const float* x = (const float*)d_in[1];
    const float* W = (const float*)d_in[2];
    const float* b = (const float*)d_in[3];
    float* out = (float*)d_out;

    // scratch symbol address (fallback sink) -- deterministic, no alloc
    float* scratch = nullptr;
    cudaGetSymbolAddress((void**)&scratch, g_scratch);

    // assumed flattened tuple layout: y | soft | hard | s_concat | 0
    const int FULL = NTOK * DDIM + 16 + 16 + NTOK * NEXP + 1;   // 6422561
    float *y, *soft, *hard, *sc, *zero;
    if (out_size == FULL) {
        y    = out;
        soft = out + NTOK * DDIM;
        hard = soft + 16;
        sc   = hard + 16;
        zero = sc + NTOK * NEXP;
    } else {
        y    = out;                 // assume y-only
        sc   = scratch;
        soft = scratch + NTOK * NEXP;
        hard = soft + 16;
        zero = hard + 16;
    }

    gate_kernel<<<GATE_BLOCKS, 256>>>(x, W, b, sc);
    combine_kernel<<<NTOK, 384>>>(f, y);
    finalize_kernel<<<1, 32>>>(soft, hard, zero);
}